// round 12
// baseline (speedup 1.0000x reference)
#include <cuda_runtime.h>
#include <cuda_fp16.h>
#include <cstdint>
#include <cstring>

#define BB 4
#define CC 256
#define HH 180
#define WW 320
#define DD 64
#define HW (HH * WW)

#define XT 128           // M tile (x per CTA)
#define NXT 3            // ceil(320/128)
#define NTILES (NXT * HH * BB)  // 2160
#define KC 16            // channels per chunk (half-chunks, prefetch dist 2)
#define NCHUNK (CC / KC) // 16
#define NTHREADS 256     // 8 warps, warp w -> rows 16w..16w+15
#define GRIDX 304        // 152 SMs x 2 CTAs, persistent

// smem (bytes). k-major, 16B-padded rows for conflict-free ldmatrix
#define SA_STRIDE 272            // 128 halfs + pad = 17 * 16B
#define SB_STRIDE 400            // 192 halfs + pad = 25 * 16B
#define SA_BYTES (KC * SA_STRIDE)        // 4352
#define SB_BYTES (KC * SB_STRIDE)        // 6400
#define SB_BASE (2 * SA_BYTES)           // 8704
#define SOUT_STRIDE 132          // floats
#define SMEM_BYTES (DD * SOUT_STRIDE * 4)  // 33792 >= 2*(SA+SB) = 21504

static __device__ __forceinline__ uint32_t smem_u32(const void* p) {
    uint32_t a;
    asm("{ .reg .u64 t; cvta.to.shared.u64 t, %1; cvt.u32.u64 %0, t; }"
        : "=r"(a) : "l"(p));
    return a;
}

static __device__ __forceinline__ void ldsm4t(uint32_t& r0, uint32_t& r1,
                                              uint32_t& r2, uint32_t& r3,
                                              uint32_t addr) {
    asm volatile("ldmatrix.sync.aligned.m8n8.x4.trans.shared.b16 {%0,%1,%2,%3}, [%4];"
                 : "=r"(r0), "=r"(r1), "=r"(r2), "=r"(r3) : "r"(addr));
}

static __device__ __forceinline__ void mma16816(float* c,
                                                uint32_t a0, uint32_t a1,
                                                uint32_t a2, uint32_t a3,
                                                uint32_t b0, uint32_t b1) {
    asm volatile("mma.sync.aligned.m16n8k16.row.col.f32.f16.f16.f32 "
                 "{%0,%1,%2,%3},{%4,%5,%6,%7},{%8,%9},{%0,%1,%2,%3};"
                 : "+f"(c[0]), "+f"(c[1]), "+f"(c[2]), "+f"(c[3])
                 : "r"(a0), "r"(a1), "r"(a2), "r"(a3), "r"(b0), "r"(b1));
}

static __device__ __forceinline__ uint32_t pack_h2(float x, float y) {
    __half2 h = __floats2half2_rn(x, y);
    uint32_t u;
    memcpy(&u, &h, 4);
    return u;
}

__global__ __launch_bounds__(NTHREADS, 2)
void cost_volume_hmma(const float* __restrict__ Lp,
                      const float* __restrict__ Rp,
                      float* __restrict__ out) {
    __shared__ __align__(16) char sBuf[SMEM_BYTES];

    const int tid = threadIdx.x;
    const int wid = tid >> 5;
    const int lid = tid & 31;

    const uint32_t sbase = smem_u32(sBuf);

    // ---- per-thread loader constants (tile-invariant) ----
    // A: 16 c-rows x 32 quads (128 x) = 512 quads, 2/thread
    const int a_xq4 = (tid & 31) * 4;
    int a_cHW[2];
#pragma unroll
    for (int p = 0; p < 2; ++p) a_cHW[p] = ((tid + p * NTHREADS) >> 5) * HW;
    // B: 16 c-rows x 48 quads (192 y) = 768 quads, 3/thread
    const int b_cHW = (tid >> 4) * HW;
    int b_yq4[3];
#pragma unroll
    for (int p = 0; p < 3; ++p) b_yq4[p] = ((tid & 15) + p * 16) * 4;

    // smem store offsets (tile-invariant)
    int a_soff[2], b_soff[3];
#pragma unroll
    for (int p = 0; p < 2; ++p) {
        int q = tid + p * NTHREADS;
        a_soff[p] = (q >> 5) * SA_STRIDE + (q & 31) * 8;
    }
#pragma unroll
    for (int p = 0; p < 3; ++p)
        b_soff[p] = (tid >> 4) * SB_STRIDE + ((tid & 15) + p * 16) * 8;

    // ---- ldmatrix per-lane offsets ----
    const uint32_t a_loff =
        (uint32_t)(((lid & 7) + ((lid >> 4) & 1) * 8) * SA_STRIDE +
                   (16 * wid + ((lid >> 3) & 1) * 8) * 2);
    const uint32_t b_loff =
        (uint32_t)(((lid & 7) + ((lid >> 3) & 1) * 8) * SB_STRIDE +
                   (16 * wid + ((lid >> 4) & 1) * 8) * 2);

    float acc[10][4];
    float4 aq[2][2], bq[2][3];   // two staging sets (prefetch distance 2)
    const float4 zero4 = make_float4(0.f, 0.f, 0.f, 0.f);

    auto ldg_chunk = [&](int s, const float* Lc, const float* Rc, int x0v) {
        const int xx = x0v + a_xq4;
        const bool aok = xx < WW;
#pragma unroll
        for (int p = 0; p < 2; ++p)
            aq[s][p] = aok ? __ldcs((const float4*)(Lc + a_cHW[p] + xx)) : zero4;
#pragma unroll
        for (int p = 0; p < 3; ++p) {
            const int y = x0v - 64 + b_yq4[p];
            bq[s][p] = (y >= 0 && y < WW) ? *(const float4*)(Rc + b_cHW + y)
                                          : zero4;
        }
    };

    auto sts_chunk = [&](int s, int buf) {
#pragma unroll
        for (int p = 0; p < 2; ++p) {
            uint2 u;
            u.x = pack_h2(aq[s][p].x, aq[s][p].y);
            u.y = pack_h2(aq[s][p].z, aq[s][p].w);
            *(uint2*)(sBuf + buf * SA_BYTES + a_soff[p]) = u;
        }
#pragma unroll
        for (int p = 0; p < 3; ++p) {
            uint2 u;
            u.x = pack_h2(bq[s][p].x, bq[s][p].y);
            u.y = pack_h2(bq[s][p].z, bq[s][p].w);
            *(uint2*)(sBuf + SB_BASE + buf * SB_BYTES + b_soff[p]) = u;
        }
    };

    auto compute = [&](int buf) {
        const uint32_t abase = sbase + (uint32_t)(buf * SA_BYTES) + a_loff;
        const uint32_t bbase = sbase + (uint32_t)(SB_BASE + buf * SB_BYTES) + b_loff;
        uint32_t a0, a1, a2, a3;
        ldsm4t(a0, a1, a2, a3, abase);
#pragma unroll
        for (int tp = 0; tp < 5; ++tp) {
            uint32_t b0, b1, b2, b3;
            ldsm4t(b0, b1, b2, b3, bbase + (uint32_t)(tp * 32));
            mma16816(acc[2 * tp],     a0, a1, a2, a3, b0, b1);
            mma16816(acc[2 * tp + 1], a0, a1, a2, a3, b2, b3);
        }
    };

    // ---- persistent tile loop ----
    int tile = blockIdx.x;
    if (tile >= NTILES) return;

    int xtile = tile % NXT;
    int hh = (tile / NXT) % HH;
    int bb = tile / (NXT * HH);
    int x0 = xtile * XT;
    const float* Lrow = Lp + (size_t)bb * CC * HW + (size_t)hh * WW;
    const float* Rrow = Rp + (size_t)bb * CC * HW + (size_t)hh * WW;

    // prologue: chunks 0,1 of first tile into staging sets 0,1
    ldg_chunk(0, Lrow, Rrow, x0);
    ldg_chunk(1, Lrow + (size_t)KC * HW, Rrow + (size_t)KC * HW, x0);

    for (;;) {
        // stage set 0 (this tile's chunk 0) -> smem buf 0
        sts_chunk(0, 0);
        __syncthreads();

#pragma unroll
        for (int t = 0; t < 10; ++t)
#pragma unroll
            for (int j = 0; j < 4; ++j) acc[t][j] = 0.0f;

        // next-tile coordinates (needed from k = NCHUNK-2)
        const int ntile = tile + GRIDX;
        const bool have_next = ntile < NTILES;
        int nxtile = 0, nhh = 0, nbb = 0, nx0 = 0;
        const float *Lnrow = Lrow, *Rnrow = Rrow;
        if (have_next) {
            nxtile = ntile % NXT;
            nhh = (ntile / NXT) % HH;
            nbb = ntile / (NXT * HH);
            nx0 = nxtile * XT;
            Lnrow = Lp + (size_t)nbb * CC * HW + (size_t)nhh * WW;
            Rnrow = Rp + (size_t)nbb * CC * HW + (size_t)nhh * WW;
        }

        // ---- mainloop: ldg(k+2) / compute(k) / sts(k+1) ----
#pragma unroll 1
        for (int k = 0; k < NCHUNK; ++k) {
            if (k + 2 < NCHUNK) {
                ldg_chunk(k & 1, Lrow + (size_t)(k + 2) * KC * HW,
                          Rrow + (size_t)(k + 2) * KC * HW, x0);
            } else if (have_next) {
                // cross-tile prefetch: next tile chunks 0 (k=14) and 1 (k=15)
                ldg_chunk(k & 1, Lnrow + (size_t)(k + 2 - NCHUNK) * KC * HW,
                          Rnrow + (size_t)(k + 2 - NCHUNK) * KC * HW, nx0);
            }
            compute(k & 1);
            if (k + 1 < NCHUNK) sts_chunk((k + 1) & 1, (k + 1) & 1);
            __syncthreads();
        }

        // ---- epilogue: diagonal remap into sOut[i][x], i = x - y ----
        // (buffers are dead here: the cross-tile carry lives in registers)
        float* sOut = (float*)sBuf;
        const float sc = 1.0f / 256.0f;
        const int g = lid >> 2;
        const int tg = lid & 3;
#pragma unroll
        for (int t = 0; t < 10; ++t) {
#pragma unroll
            for (int j = 0; j < 4; ++j) {
                const int r = g + (j >> 1) * 8;
                const int cn = 2 * tg + (j & 1);
                const int i = r + 64 - 8 * t - cn;   // disparity
                if (i >= 0 && i < DD)
                    sOut[i * SOUT_STRIDE + 16 * wid + r] = acc[t][j] * sc;
            }
        }
        __syncthreads();

        // ---- coalesced float4 streaming stores ----
        {
            const int xl4 = lid * 4;
            if (x0 + xl4 < WW) {
#pragma unroll
                for (int i = wid; i < DD; i += 8) {
                    float4 v = *(const float4*)&sOut[i * SOUT_STRIDE + xl4];
                    __stcs((float4*)&out[(((size_t)bb * DD + i) * HH + hh) * WW +
                                         x0 + xl4], v);
                }
            }
        }

        if (!have_next) break;
        __syncthreads();   // sOut reads done before next tile's sts overwrites

        tile = ntile;
        xtile = nxtile; hh = nhh; bb = nbb; x0 = nx0;
        Lrow = Lnrow; Rrow = Rnrow;
    }
}

extern "C" void kernel_launch(void* const* d_in, const int* in_sizes, int n_in,
                              void* d_out, int out_size) {
    const float* left  = (const float*)d_in[0];
    const float* right = (const float*)d_in[1];
    float* out = (float*)d_out;
    (void)in_sizes; (void)n_in; (void)out_size;

    dim3 grid(GRIDX);          // persistent: 152 SMs x 2 CTAs
    dim3 block(NTHREADS);
    cost_volume_hmma<<<grid, block>>>(left, right, out);
}

// round 13
// speedup vs baseline: 1.9973x; 1.9973x over previous
#include <cuda_runtime.h>
#include <cuda_fp16.h>
#include <cstdint>
#include <cstring>

#define BB 4
#define CC 256
#define HH 180
#define WW 320
#define DD 64
#define HW (HH * WW)

#define XT 128            // M tile (x per CTA)
#define NXT 3             // ceil(320/128)
#define NTILES (NXT * HH * BB)   // 2160
#define KC 16             // channels per chunk
#define NCHUNK 16         // CC / KC
#define NTHREADS 256      // 8 warps, warp w -> rows 16w..16w+15
#define GRIDX 304         // 152 SMs x 2 CTAs, persistent

// ---- dynamic smem layout (bytes) ----
// fp32 ring: 4 stages x (A 16x128 fp32 = 8192 | B 16x192 fp32 = 12288)
#define ST_A 8192
#define ST_B 12288
#define STAGE (ST_A + ST_B)       // 20480
#define NSTAGE 4
#define RING (NSTAGE * STAGE)     // 81920
// fp16 double buffers (ldmatrix layout, padded rows)
#define SA_STRIDE 272             // 128 halfs + 16B pad
#define SB_STRIDE 400             // 192 halfs + 16B pad
#define SA16 (KC * SA_STRIDE)     // 4352
#define SB16 (KC * SB_STRIDE)     // 6400
#define FA_BASE RING
#define FB_BASE (RING + 2 * SA16)
#define SMEM_TOTAL (RING + 2 * SA16 + 2 * SB16)   // 103424
// epilogue scratch overlays ring slots 2,3 (only slot 1 is in flight then)
#define SOUT_OFF (2 * STAGE)      // 40960
#define SOUT_STRIDE 132           // floats; 64*132*4 = 33792 <= 40960

static __device__ __forceinline__ uint32_t smem_u32(const void* p) {
    uint32_t a;
    asm("{ .reg .u64 t; cvta.to.shared.u64 t, %1; cvt.u32.u64 %0, t; }"
        : "=r"(a) : "l"(p));
    return a;
}

static __device__ __forceinline__ void cpa16(uint32_t dst, const float* src,
                                             int srcbytes) {
    asm volatile("cp.async.cg.shared.global [%0], [%1], 16, %2;\n"
                 :: "r"(dst), "l"(src), "r"(srcbytes));
}
static __device__ __forceinline__ void cpa_commit() {
    asm volatile("cp.async.commit_group;\n" ::: "memory");
}
static __device__ __forceinline__ void cpa_wait1() {
    asm volatile("cp.async.wait_group 1;\n" ::: "memory");
}
static __device__ __forceinline__ void cpa_wait0() {
    asm volatile("cp.async.wait_group 0;\n" ::: "memory");
}

static __device__ __forceinline__ void ldsm4t(uint32_t& r0, uint32_t& r1,
                                              uint32_t& r2, uint32_t& r3,
                                              uint32_t addr) {
    asm volatile("ldmatrix.sync.aligned.m8n8.x4.trans.shared.b16 {%0,%1,%2,%3}, [%4];"
                 : "=r"(r0), "=r"(r1), "=r"(r2), "=r"(r3) : "r"(addr));
}

static __device__ __forceinline__ void mma16816(float* c,
                                                uint32_t a0, uint32_t a1,
                                                uint32_t a2, uint32_t a3,
                                                uint32_t b0, uint32_t b1) {
    asm volatile("mma.sync.aligned.m16n8k16.row.col.f32.f16.f16.f32 "
                 "{%0,%1,%2,%3},{%4,%5,%6,%7},{%8,%9},{%0,%1,%2,%3};"
                 : "+f"(c[0]), "+f"(c[1]), "+f"(c[2]), "+f"(c[3])
                 : "r"(a0), "r"(a1), "r"(a2), "r"(a3), "r"(b0), "r"(b1));
}

static __device__ __forceinline__ uint32_t pack_h2(float x, float y) {
    __half2 h = __floats2half2_rn(x, y);
    uint32_t u;
    memcpy(&u, &h, 4);
    return u;
}

__global__ __launch_bounds__(NTHREADS, 2)
void cost_volume_hmma(const float* __restrict__ Lp,
                      const float* __restrict__ Rp,
                      float* __restrict__ out) {
    extern __shared__ __align__(16) char dyn[];
    const uint32_t base = smem_u32(dyn);

    const int tid = threadIdx.x;
    const int wid = tid >> 5;
    const int lid = tid & 31;
    const int bid = blockIdx.x;

    // ---- tile-invariant per-thread offsets ----
    // A: 512 quads (16 rows x 32), 2/thread: row = (tid>>5)+8p, col = tid&31
    const int acol = tid & 31;
    int a_rowHW[2], a_sdst[2], a_fdst[2];
#pragma unroll
    for (int p = 0; p < 2; ++p) {
        const int r = (tid >> 5) + 8 * p;
        a_rowHW[p] = r * HW;
        a_sdst[p] = r * 512 + acol * 16;           // fp32 stage (A at +0)
        a_fdst[p] = r * SA_STRIDE + acol * 8;      // fp16 buf
    }
    // B: 768 quads (16 rows x 48), 3/thread: q = tid + 256p
    int b_rowHW[3], b_sdst[3], b_fdst[3], b_col4[3];
#pragma unroll
    for (int p = 0; p < 3; ++p) {
        const int q = tid + p * NTHREADS;
        const int r = q / 48, c = q % 48;
        b_rowHW[p] = r * HW;
        b_sdst[p] = ST_A + r * 768 + c * 16;       // fp32 stage (B at +ST_A)
        b_fdst[p] = r * SB_STRIDE + c * 8;
        b_col4[p] = c * 4;
    }

    // ---- ldmatrix per-lane offsets ----
    const uint32_t a_loff =
        (uint32_t)(((lid & 7) + ((lid >> 4) & 1) * 8) * SA_STRIDE +
                   (16 * wid + ((lid >> 3) & 1) * 8) * 2);
    const uint32_t b_loff =
        (uint32_t)(((lid & 7) + ((lid >> 3) & 1) * 8) * SB_STRIDE +
                   (16 * wid + ((lid >> 4) & 1) * 8) * 2);

    float acc[10][4];
#pragma unroll
    for (int t = 0; t < 10; ++t)
#pragma unroll
        for (int j = 0; j < 4; ++j) acc[t][j] = 0.0f;

    // ---- issue-side tile state ----
    const float* LtTile = nullptr;
    const float* RtTile = nullptr;
    int a_gx = 0;
    bool aok = false;
    int b_gy[3];
    bool bok[3];

    auto set_issue_tile = [&](int tOrd) {
        const int tileId = bid + tOrd * GRIDX;
        const int xtile = tileId % NXT;
        const int hh = (tileId / NXT) % HH;
        const int bb = tileId / (NXT * HH);
        const int x0 = xtile * XT;
        LtTile = Lp + (size_t)bb * CC * HW + (size_t)hh * WW;
        RtTile = Rp + (size_t)bb * CC * HW + (size_t)hh * WW;
        a_gx = x0 + acol * 4;
        aok = a_gx < WW;
#pragma unroll
        for (int p = 0; p < 3; ++p) {
            b_gy[p] = x0 - 64 + b_col4[p];
            bok[p] = (b_gy[p] >= 0) && (b_gy[p] < WW);
        }
    };

    auto issue_chunk = [&](int c) {
        const int cc = c & 15;
        if (cc == 0) set_issue_tile(c >> 4);
        const uint32_t sb = base + (uint32_t)((c & 3) * STAGE);
        const float* Lc = LtTile + (size_t)cc * KC * HW;
        const float* Rc = RtTile + (size_t)cc * KC * HW;
#pragma unroll
        for (int p = 0; p < 2; ++p)
            cpa16(sb + a_sdst[p], aok ? (Lc + a_rowHW[p] + a_gx) : Lp,
                  aok ? 16 : 0);
#pragma unroll
        for (int p = 0; p < 3; ++p)
            cpa16(sb + b_sdst[p], bok[p] ? (Rc + b_rowHW[p] + b_gy[p]) : Rp,
                  bok[p] ? 16 : 0);
        cpa_commit();
    };

    auto convert_chunk = [&](int c) {
        const char* sb = dyn + (c & 3) * STAGE;
        char* fa = dyn + FA_BASE + (c & 1) * SA16;
        char* fb = dyn + FB_BASE + (c & 1) * SB16;
#pragma unroll
        for (int p = 0; p < 2; ++p) {
            float4 v = *(const float4*)(sb + a_sdst[p]);
            uint2 u;
            u.x = pack_h2(v.x, v.y);
            u.y = pack_h2(v.z, v.w);
            *(uint2*)(fa + a_fdst[p]) = u;
        }
#pragma unroll
        for (int p = 0; p < 3; ++p) {
            float4 v = *(const float4*)(sb + b_sdst[p]);
            uint2 u;
            u.x = pack_h2(v.x, v.y);
            u.y = pack_h2(v.z, v.w);
            *(uint2*)(fb + b_fdst[p]) = u;
        }
    };

    auto compute = [&](int buf) {
        const uint32_t abase = base + FA_BASE + (uint32_t)(buf * SA16) + a_loff;
        const uint32_t bbase = base + FB_BASE + (uint32_t)(buf * SB16) + b_loff;
        uint32_t a0, a1, a2, a3;
        ldsm4t(a0, a1, a2, a3, abase);
#pragma unroll
        for (int tp = 0; tp < 5; ++tp) {
            uint32_t b0, b1, b2, b3;
            ldsm4t(b0, b1, b2, b3, bbase + (uint32_t)(tp * 32));
            mma16816(acc[2 * tp],     a0, a1, a2, a3, b0, b1);
            mma16816(acc[2 * tp + 1], a0, a1, a2, a3, b2, b3);
        }
    };

    const int myTiles = (NTILES - bid + GRIDX - 1) / GRIDX;
    const int gEnd = myTiles * NCHUNK;

    // ---- prologue: chunks 0,1 in flight; convert chunk 0 ----
    issue_chunk(0);
    issue_chunk(1);
    cpa_wait1();          // chunk 0 arrived
    convert_chunk(0);
    __syncthreads();

    // ---- unified chunk-stream loop ----
#pragma unroll 1
    for (int g = 0; g < gEnd; ++g) {
        const int c = g + 2;
        const bool did_issue = (c < gEnd);
        if (did_issue) issue_chunk(c);

        compute(g & 1);

        if (g + 1 < gEnd) {
            if (did_issue) cpa_wait1();   // pending {g+1, g+2} -> g+1 ready
            else           cpa_wait0();   // pending {g+1} only
            convert_chunk(g + 1);
        }
        __syncthreads();

        if ((g & 15) == 15) {
            // ---- epilogue for tile g>>4 ----
            const int tileId = bid + (g >> 4) * GRIDX;
            const int xtile = tileId % NXT;
            const int hh = (tileId / NXT) % HH;
            const int bb = tileId / (NXT * HH);
            const int x0 = xtile * XT;

            float* sOut = (float*)(dyn + SOUT_OFF);
            const float sc = 1.0f / 256.0f;
            const int gq = lid >> 2;
            const int tg = lid & 3;
#pragma unroll
            for (int t = 0; t < 10; ++t) {
#pragma unroll
                for (int j = 0; j < 4; ++j) {
                    const int r = gq + (j >> 1) * 8;
                    const int cn = 2 * tg + (j & 1);
                    const int i = r + 64 - 8 * t - cn;
                    if (i >= 0 && i < DD)
                        sOut[i * SOUT_STRIDE + 16 * wid + r] = acc[t][j] * sc;
                }
            }
            __syncthreads();
            {
                const int xl4 = lid * 4;
                if (x0 + xl4 < WW) {
#pragma unroll
                    for (int i = wid; i < DD; i += 8) {
                        float4 v = *(const float4*)&sOut[i * SOUT_STRIDE + xl4];
                        __stcs((float4*)&out[(((size_t)bb * DD + i) * HH + hh) * WW +
                                             x0 + xl4], v);
                    }
                }
            }
            __syncthreads();   // sOut reads done before slot-2 cp.async next iter

#pragma unroll
            for (int t = 0; t < 10; ++t)
#pragma unroll
                for (int j = 0; j < 4; ++j) acc[t][j] = 0.0f;
        }
    }
}

extern "C" void kernel_launch(void* const* d_in, const int* in_sizes, int n_in,
                              void* d_out, int out_size) {
    const float* left  = (const float*)d_in[0];
    const float* right = (const float*)d_in[1];
    float* out = (float*)d_out;
    (void)in_sizes; (void)n_in; (void)out_size;

    cudaFuncSetAttribute(cost_volume_hmma,
                         cudaFuncAttributeMaxDynamicSharedMemorySize, SMEM_TOTAL);
    dim3 grid(GRIDX);
    dim3 block(NTHREADS);
    cost_volume_hmma<<<grid, block, SMEM_TOTAL>>>(left, right, out);
}